// round 12
// baseline (speedup 1.0000x reference)
#include <cuda_runtime.h>
#include <math.h>

#define BH   16
#define NSEQ 2048
#define DH   64
#define MF   256
#define CH   64
#define NC   (NSEQ/CH)
#define CSUM (MF*DH + MF)

#define NORMALIZER 0.35355339059327373f  // 64^-0.25
#define RATIO      0.0625f               // 256^-0.5
#define EPSK       1e-4f
#define EPSD       1e-6f

typedef unsigned long long ull;

__device__ __align__(16) float g_qp[BH*NSEQ*MF];   // phi(q) stored as tf32 BIT PATTERNS
__device__ __align__(16) float g_kp[BH*NSEQ*MF];   // xd-diag (fp32) -> phi(k) tf32 bits after chunksum
__device__ __align__(16) float g_kmax[BH];
__device__ __align__(16) float g_csum[BH*NC*CSUM]; // CtxT[d][m] + ksum[m] per chunk, exclusive-prefixed

__device__ __forceinline__ unsigned f2tf(float f) {
    unsigned u; asm("cvt.rna.tf32.f32 %0, %1;" : "=r"(u) : "f"(f)); return u;
}
__device__ __forceinline__ void mma8(float c[4], unsigned a0, unsigned a1,
                                     unsigned a2, unsigned a3,
                                     unsigned b0, unsigned b1) {
    asm("mma.sync.aligned.m16n8k8.row.col.f32.tf32.tf32.f32 "
        "{%0,%1,%2,%3},{%4,%5,%6,%7},{%8,%9},{%0,%1,%2,%3};"
        : "+f"(c[0]), "+f"(c[1]), "+f"(c[2]), "+f"(c[3])
        : "r"(a0), "r"(a1), "r"(a2), "r"(a3), "r"(b0), "r"(b1));
}
__device__ __forceinline__ void atomicMaxF(float* addr, float val) {
    int old = __float_as_int(*addr);
    while (val > __int_as_float(old)) {
        int assumed = old;
        old = atomicCAS((int*)addr, assumed, __float_as_int(val));
        if (old == assumed) break;
    }
}

__global__ void init_kernel() {
    if (threadIdx.x < BH) g_kmax[threadIdx.x] = -3.0e38f;
}

// ---------------- fused proj: compensated tf32 mma, q + k passes (R10) ----------------
__global__ __launch_bounds__(512) void proj_kernel(const float* __restrict__ q,
                                                   const float* __restrict__ k,
                                                   const float* __restrict__ proj) {
    int head = blockIdx.x >> 4;
    int t0   = (blockIdx.x & 15) * 128;
    int tid  = threadIdx.x;
    int lane = tid & 31, warp = tid >> 5;
    int gid  = lane >> 2, tg = lane & 3;
    int mt   = warp & 7;
    int nh   = warp >> 3;

    extern __shared__ unsigned psm[];
    unsigned* uph = psm;                // [256][72] proj hi
    unsigned* upl = psm + 256*72;       // [256][72] proj lo
    unsigned* uxh = psm + 2*256*72;     // [128][72] x hi
    unsigned* uxl = uxh + 128*72;       // [128][72] x lo
    __shared__ float diag_s[128];
    __shared__ float mx_s[128];
    __shared__ float red_s[256];

    for (int i = tid; i < MF*DH; i += 512) {
        int r = i >> 6, d = i & 63;
        float f = proj[i];
        unsigned hi = f2tf(f);
        uph[r*72 + d] = hi;
        upl[r*72 + d] = f2tf(f - __uint_as_float(hi));
    }

#pragma unroll
    for (int pass = 0; pass < 2; pass++) {
        const float* x = (pass == 0) ? q : k;
        const float* xb = x + ((size_t)head*NSEQ + t0)*DH;
        __syncthreads();
        for (int i = tid; i < 128*DH; i += 512) {
            int r = i >> 6, d = i & 63;
            float f = NORMALIZER * xb[i];
            unsigned hi = f2tf(f);
            uxh[r*72 + d] = hi;
            uxl[r*72 + d] = f2tf(f - __uint_as_float(hi));
        }
        __syncthreads();
        if (tid < 128) {
            float s = 0.f;
#pragma unroll 8
            for (int d = 0; d < DH; d++) {
                float vv = __uint_as_float(uxh[tid*72 + d]) + __uint_as_float(uxl[tid*72 + d]);
                s += vv*vv;
            }
            diag_s[tid] = 0.5f * s;
        }

        float acc[16][4];
#pragma unroll
        for (int j = 0; j < 16; j++)
#pragma unroll
            for (int r = 0; r < 4; r++) acc[j][r] = 0.f;

#pragma unroll
        for (int k0 = 0; k0 < DH; k0 += 8) {
            uint2 ah01 = *(const uint2*)&uxh[(mt*16 + gid    )*72 + k0 + 2*tg];
            uint2 ah23 = *(const uint2*)&uxh[(mt*16 + gid + 8)*72 + k0 + 2*tg];
            uint2 al01 = *(const uint2*)&uxl[(mt*16 + gid    )*72 + k0 + 2*tg];
            uint2 al23 = *(const uint2*)&uxl[(mt*16 + gid + 8)*72 + k0 + 2*tg];
#pragma unroll
            for (int jj = 0; jj < 16; jj++) {
                int row = (nh*16 + jj)*8 + gid;
                uint2 bh = *(const uint2*)&uph[row*72 + k0 + 2*tg];
                uint2 bl = *(const uint2*)&upl[row*72 + k0 + 2*tg];
                mma8(acc[jj], ah01.x, ah23.x, ah01.y, ah23.y, bh.x, bh.y);
                mma8(acc[jj], ah01.x, ah23.x, ah01.y, ah23.y, bl.x, bl.y);
                mma8(acc[jj], al01.x, al23.x, al01.y, al23.y, bh.x, bh.y);
            }
        }

        int row0 = mt*16 + gid, row1 = row0 + 8;
        if (pass == 0) {
            float m0 = -3.0e38f, m1 = -3.0e38f;
#pragma unroll
            for (int jj = 0; jj < 16; jj++) {
                m0 = fmaxf(m0, fmaxf(acc[jj][0], acc[jj][1]));
                m1 = fmaxf(m1, fmaxf(acc[jj][2], acc[jj][3]));
            }
            m0 = fmaxf(m0, __shfl_xor_sync(0xffffffffu, m0, 1));
            m0 = fmaxf(m0, __shfl_xor_sync(0xffffffffu, m0, 2));
            m1 = fmaxf(m1, __shfl_xor_sync(0xffffffffu, m1, 1));
            m1 = fmaxf(m1, __shfl_xor_sync(0xffffffffu, m1, 2));
            if (tg == 0) {
                red_s[nh*128 + row0] = m0;
                red_s[nh*128 + row1] = m1;
            }
            __syncthreads();
            if (tid < 128) mx_s[tid] = fmaxf(red_s[tid], red_s[128 + tid]);
            __syncthreads();
            float d0 = diag_s[row0] + mx_s[row0];
            float d1 = diag_s[row1] + mx_s[row1];
            unsigned* ob = (unsigned*)g_qp + ((size_t)head*NSEQ + t0)*MF;
#pragma unroll
            for (int jj = 0; jj < 16; jj++) {
                int f0 = (nh*16 + jj)*8 + 2*tg;
                // store phi(q) as tf32 bit patterns (mma-ready)
                uint2 w0 = make_uint2(f2tf(RATIO*(__expf(acc[jj][0] - d0) + EPSK)),
                                      f2tf(RATIO*(__expf(acc[jj][1] - d0) + EPSK)));
                uint2 w1 = make_uint2(f2tf(RATIO*(__expf(acc[jj][2] - d1) + EPSK)),
                                      f2tf(RATIO*(__expf(acc[jj][3] - d1) + EPSK)));
                *(uint2*)&ob[(size_t)row0*MF + f0] = w0;
                *(uint2*)&ob[(size_t)row1*MF + f0] = w1;
            }
        } else {
            float lm = -3.0e38f;
#pragma unroll
            for (int jj = 0; jj < 16; jj++) {
                lm = fmaxf(lm, fmaxf(fmaxf(acc[jj][0], acc[jj][1]),
                                     fmaxf(acc[jj][2], acc[jj][3])));
            }
#pragma unroll
            for (int o = 16; o >= 1; o >>= 1) lm = fmaxf(lm, __shfl_xor_sync(0xffffffffu, lm, o));
            if (lane == 0) red_s[warp] = lm;
            float d0 = diag_s[row0], d1 = diag_s[row1];
            float* ob = g_kp + ((size_t)head*NSEQ + t0)*MF;
#pragma unroll
            for (int jj = 0; jj < 16; jj++) {
                int f0 = (nh*16 + jj)*8 + 2*tg;
                *(float2*)&ob[(size_t)row0*MF + f0] = make_float2(acc[jj][0]-d0, acc[jj][1]-d0);
                *(float2*)&ob[(size_t)row1*MF + f0] = make_float2(acc[jj][2]-d1, acc[jj][3]-d1);
            }
            __syncthreads();
            if (tid == 0) {
                float mx = red_s[0];
                for (int r = 1; r < 16; r++) mx = fmaxf(mx, red_s[r]);
                atomicMaxF(&g_kmax[head], mx);
            }
        }
    }
}

// ---------------- chunksum: tf32 mma; writes phi(k) back as tf32 bits ----------------
__global__ __launch_bounds__(256) void chunksum_kernel(const float* __restrict__ v) {
    int head = blockIdx.x / NC, c = blockIdx.x % NC, t0 = c*CH, tid = threadIdx.x;
    extern __shared__ unsigned cs_u[];
    unsigned* uphi = cs_u;            // [256][72] tf32, [m][t]
    unsigned* uvT  = cs_u + 256*72;   // [64][72]  tf32, [d][t]

    const float* vb = v + ((size_t)head*NSEQ + t0)*DH;
    for (int i = tid; i < CH*DH; i += 256) {
        int t = i >> 6, d = i & 63;
        uvT[d*72 + t] = f2tf(vb[i]);
    }
    float kmax = g_kmax[head];
    float* kpb = g_kp + ((size_t)head*NSEQ + t0)*MF;
    for (int i = tid; i < CH*MF; i += 256) {
        int t = i >> 8, m = i & 255;
        float phi = RATIO * (__expf(kpb[i] - kmax) + EPSK);
        unsigned tb = f2tf(phi);
        kpb[i] = __uint_as_float(tb);     // tf32 bits -> out_kernel copies raw
        uphi[m*72 + t] = tb;
    }
    __syncthreads();

    int lane = tid & 31, warp = tid >> 5, gid = lane >> 2, tg = lane & 3;
    int mt = warp >> 1, nh = warp & 1;

    float acc[16][4];
#pragma unroll
    for (int j = 0; j < 16; j++)
#pragma unroll
        for (int r = 0; r < 4; r++) acc[j][r] = 0.f;

#pragma unroll
    for (int k0 = 0; k0 < CH; k0 += 8) {
        uint2 a01 = *(const uint2*)&uvT[(mt*16 + gid    )*72 + k0 + 2*tg];
        uint2 a23 = *(const uint2*)&uvT[(mt*16 + gid + 8)*72 + k0 + 2*tg];
#pragma unroll
        for (int j = 0; j < 16; j++) {
            int m0 = (nh*16 + j)*8;
            uint2 bb = *(const uint2*)&uphi[(m0 + gid)*72 + k0 + 2*tg];
            mma8(acc[j], a01.x, a23.x, a01.y, a23.y, bb.x, bb.y);
        }
    }
    float* ob = g_csum + (size_t)(head*NC + c)*CSUM;
#pragma unroll
    for (int j = 0; j < 16; j++) {
        int m = (nh*16 + j)*8 + 2*tg;
        int d = mt*16 + gid;
        *(float2*)&ob[(size_t)d*MF + m]       = make_float2(acc[j][0], acc[j][1]);
        *(float2*)&ob[(size_t)(d + 8)*MF + m] = make_float2(acc[j][2], acc[j][3]);
    }
    if (tid < MF) {
        float s = 0.f;
#pragma unroll 8
        for (int tt = 0; tt < CH; tt++)
            s += __uint_as_float(uphi[tid*72 + (tt ^ (tid >> 2 & 7))]);
        ob[MF*DH + tid] = s;
    }
}

// Exclusive prefix over chunks (R10 version). grid (BH, 65).
__global__ __launch_bounds__(256) void prefix_kernel() {
    int head = blockIdx.x;
    int idx  = blockIdx.y*256 + threadIdx.x;   // 65*256 = CSUM
    float* base = g_csum + (size_t)head*NC*CSUM + idx;
    float vals[NC];
#pragma unroll
    for (int cc = 0; cc < NC; cc++) vals[cc] = base[(size_t)cc*CSUM];
    float run = 0.f;
#pragma unroll
    for (int cc = 0; cc < NC; cc++) { base[(size_t)cc*CSUM] = run; run += vals[cc]; }
}

// ---------------- out: tf32 mma, uint4 staging (R10 structure, 256 threads) ----------------
__global__ __launch_bounds__(256) void out_kernel(const float* __restrict__ v,
                                                  float* __restrict__ out) {
    int head = blockIdx.x / NC, c = blockIdx.x % NC, t0 = c*CH, tid = threadIdx.x;
    extern __shared__ unsigned osm[];
    unsigned* uq  = osm;            // [64][264] tf32 Q'
    unsigned* upT = osm + 16896;    // [80][264] PT+spref row; aliases K' in phase 1
    unsigned* uvT = osm + 38016;    // [80][72]  VT + ones row
    unsigned* uS  = osm + 43776;    // [64][72]  masked S^T
    unsigned* uk  = upT;

    // Q'/K' are tf32 bits in gmem -> pure 128-bit copies, no cvt
    const uint4* qg4 = reinterpret_cast<const uint4*>(g_qp + ((size_t)head*NSEQ + t0)*MF);
    const uint4* kg4 = reinterpret_cast<const uint4*>(g_kp + ((size_t)head*NSEQ + t0)*MF);
    for (int i = tid; i < CH*MF/4; i += 256) {
        int t = i >> 6, m4 = (i & 63)*4;       // 64 uint4 per 256-wide row
        *(uint4*)&uq[t*264 + m4] = qg4[i];
        *(uint4*)&uk[t*264 + m4] = kg4[i];
    }
    const float* vb = v + ((size_t)head*NSEQ + t0)*DH;
    for (int i = tid; i < CH*DH; i += 256) {
        int t = i >> 6, d = i & 63;
        uvT[d*72 + t] = f2tf(vb[i]);
    }
    for (int i = tid; i < 16*72; i += 256) {
        int r = 64 + i/72, t = i % 72;
        uvT[r*72 + t] = (r == 64 && t < CH) ? 0x3f800000u : 0u;
    }
    __syncthreads();

    int lane = tid & 31, warp = tid >> 5, gid = lane >> 2, tg = lane & 3;

    // ---- phase 1: S^T[key][q], causal-masked ----
    {
        int mt = warp >> 1, nh = warp & 1;
        float sacc[4][4];
#pragma unroll
        for (int j = 0; j < 4; j++)
#pragma unroll
            for (int r = 0; r < 4; r++) sacc[j][r] = 0.f;

#pragma unroll 4
        for (int k0 = 0; k0 < MF; k0 += 8) {
            uint2 a01 = *(const uint2*)&uk[(mt*16 + gid    )*264 + k0 + 2*tg];
            uint2 a23 = *(const uint2*)&uk[(mt*16 + gid + 8)*264 + k0 + 2*tg];
#pragma unroll
            for (int j = 0; j < 4; j++) {
                int q0 = nh*32 + j*8;
                uint2 bb = *(const uint2*)&uq[(q0 + gid)*264 + k0 + 2*tg];
                mma8(sacc[j], a01.x, a23.x, a01.y, a23.y, bb.x, bb.y);
            }
        }
#pragma unroll
        for (int j = 0; j < 4; j++) {
            int q0  = nh*32 + j*8 + 2*tg;
            int key = mt*16 + gid;
            unsigned m00 = (key     <= q0    ) ? f2tf(sacc[j][0]) : 0u;
            unsigned m01 = (key     <= q0 + 1) ? f2tf(sacc[j][1]) : 0u;
            unsigned m10 = (key + 8 <= q0    ) ? f2tf(sacc[j][2]) : 0u;
            unsigned m11 = (key + 8 <= q0 + 1) ? f2tf(sacc[j][3]) : 0u;
            *(uint2*)&uS[(key    )*72 + q0] = make_uint2(m00, m01);
            *(uint2*)&uS[(key + 8)*72 + q0] = make_uint2(m10, m11);
        }
    }
    __syncthreads();

    // stage P^T (+ spref+eps row 64, zeros 65..79) over K' region; float4 -> uint4
    const float* pb = g_csum + (size_t)(head*NC + c)*CSUM;
    const float4* pb4 = reinterpret_cast<const float4*>(pb);
    for (int i = tid; i < MF*DH/4; i += 256) {
        int d = i >> 6, m4 = (i & 63)*4;
        float4 pv = pb4[i];
        *(uint4*)&upT[d*264 + m4] =
            make_uint4(f2tf(pv.x), f2tf(pv.y), f2tf(pv.z), f2tf(pv.w));
    }
    for (int m = tid; m < MF; m += 256) upT[64*264 + m] = f2tf(pb[MF*DH + m] + EPSD);
    for (int i = tid; i < 15*MF; i += 256) {
        int r = 65 + i/MF, m = i % MF;
        upT[r*264 + m] = 0u;
    }
    __syncthreads();

    // ---- phase 2: O^T = VT_ext@S^T + PT_ext@Q'^T ; row 64 = den ----
    {
        int q0 = warp * 8;
        float co[5][4];
#pragma unroll
        for (int mt = 0; mt < 5; mt++)
#pragma unroll
            for (int r = 0; r < 4; r++) co[mt][r] = 0.f;

#pragma unroll
        for (int k0 = 0; k0 < CH; k0 += 8) {
            unsigned b0 = uS[(k0 + 2*tg    )*72 + q0 + gid];
            unsigned b1 = uS[(k0 + 2*tg + 1)*72 + q0 + gid];
#pragma unroll
            for (int mt = 0; mt < 5; mt++) {
                uint2 a01 = *(const uint2*)&uvT[(mt*16 + gid    )*72 + k0 + 2*tg];
                uint2 a23 = *(const uint2*)&uvT[(mt*16 + gid + 8)*72 + k0 + 2*tg];
                mma8(co[mt], a01.x, a23.x, a01.y, a23.y, b0, b1);
            }
        }
#pragma unroll 4
        for (int k0 = 0; k0 < MF; k0 += 8) {
            uint2 bb = *(const uint2*)&uq[(q0 + gid)*264 + k0 + 2*tg];
#pragma unroll
            for (int mt = 0; mt < 5; mt++) {
                uint2 a01 = *(const uint2*)&upT[(mt*16 + gid    )*264 + k0 + 2*tg];
                uint2 a23 = *(const uint2*)&upT[(mt*16 + gid + 8)*264 + k0 + 2*tg];
                mma8(co[mt], a01.x, a23.x, a01.y, a23.y, bb.x, bb.y);
            }
        }
        float den0 = __shfl_sync(0xffffffffu, co[4][0], tg);
        float den1 = __shfl_sync(0xffffffffu, co[4][1], tg);
        float i0 = 1.f/den0, i1 = 1.f/den1;
        float* ob = out + ((size_t)head*NSEQ + t0)*DH;
        int qq = q0 + 2*tg;
#pragma unroll
        for (int mt = 0; mt < 4; mt++) {
            int d = mt*16 + gid;
            ob[(size_t)(qq    )*DH + d    ] = co[mt][0]*i0;
            ob[(size_t)(qq + 1)*DH + d    ] = co[mt][1]*i1;
            ob[(size_t)(qq    )*DH + d + 8] = co[mt][2]*i0;
            ob[(size_t)(qq + 1)*DH + d + 8] = co[mt][3]*i1;
        }
    }
}

extern "C" void kernel_launch(void* const* d_in, const int* in_sizes, int n_in,
                              void* d_out, int out_size) {
    const float* q    = (const float*)d_in[0];
    const float* k    = (const float*)d_in[1];
    const float* v    = (const float*)d_in[2];
    const float* proj = (const float*)d_in[3];
    float* out = (float*)d_out;

    size_t smem_pr  = (size_t)(2*256*72 + 2*128*72) * sizeof(unsigned);             // 221184
    size_t smem_cs  = (size_t)(256*72 + 64*72) * sizeof(unsigned);                  // 92160
    size_t smem_out = (size_t)(16896 + 21120 + 5760 + 4608) * sizeof(unsigned);     // 193536
    cudaFuncSetAttribute(proj_kernel,     cudaFuncAttributeMaxDynamicSharedMemorySize, (int)smem_pr);
    cudaFuncSetAttribute(chunksum_kernel, cudaFuncAttributeMaxDynamicSharedMemorySize, (int)smem_cs);
    cudaFuncSetAttribute(out_kernel,      cudaFuncAttributeMaxDynamicSharedMemorySize, (int)smem_out);

    init_kernel<<<1, 32>>>();
    proj_kernel<<<BH*16, 512, smem_pr>>>(q, k, proj);
    chunksum_kernel<<<BH*NC, 256, smem_cs>>>(v);
    prefix_kernel<<<dim3(BH, 65), 256>>>();
    out_kernel<<<BH*NC, 256, smem_out>>>(v, out);
}

// round 14
// speedup vs baseline: 1.5742x; 1.5742x over previous
#include <cuda_runtime.h>
#include <math.h>

#define BH   16
#define NSEQ 2048
#define DH   64
#define MF   256
#define CH   64
#define NC   (NSEQ/CH)
#define CSUM (MF*DH + MF)

#define NORMALIZER 0.35355339059327373f  // 64^-0.25
#define RATIO      0.0625f               // 256^-0.5
#define EPSK       1e-4f
#define EPSD       1e-6f

typedef unsigned long long ull;

__device__ __align__(16) float g_qp[BH*NSEQ*MF];   // phi(q) stored as tf32 BIT PATTERNS
__device__ __align__(16) float g_kp[BH*NSEQ*MF];   // xd-diag (fp32) -> phi(k) tf32 bits after chunksum
__device__ __align__(16) float g_kmax[BH];
__device__ __align__(16) float g_csum[BH*NC*CSUM]; // CtxT[d][m] + ksum[m] per chunk, exclusive-prefixed

__device__ __forceinline__ unsigned f2tf(float f) {
    unsigned u; asm("cvt.rna.tf32.f32 %0, %1;" : "=r"(u) : "f"(f)); return u;
}
__device__ __forceinline__ void mma8(float c[4], unsigned a0, unsigned a1,
                                     unsigned a2, unsigned a3,
                                     unsigned b0, unsigned b1) {
    asm("mma.sync.aligned.m16n8k8.row.col.f32.tf32.tf32.f32 "
        "{%0,%1,%2,%3},{%4,%5,%6,%7},{%8,%9},{%0,%1,%2,%3};"
        : "+f"(c[0]), "+f"(c[1]), "+f"(c[2]), "+f"(c[3])
        : "r"(a0), "r"(a1), "r"(a2), "r"(a3), "r"(b0), "r"(b1));
}
__device__ __forceinline__ void atomicMaxF(float* addr, float val) {
    int old = __float_as_int(*addr);
    while (val > __int_as_float(old)) {
        int assumed = old;
        old = atomicCAS((int*)addr, assumed, __float_as_int(val));
        if (old == assumed) break;
    }
}

__global__ void init_kernel() {
    if (threadIdx.x < BH) g_kmax[threadIdx.x] = -3.0e38f;
}

// ---------------- fused proj: compensated tf32 mma, q + k passes ----------------
__global__ __launch_bounds__(512) void proj_kernel(const float* __restrict__ q,
                                                   const float* __restrict__ k,
                                                   const float* __restrict__ proj) {
    int head = blockIdx.x >> 4;
    int t0   = (blockIdx.x & 15) * 128;
    int tid  = threadIdx.x;
    int lane = tid & 31, warp = tid >> 5;
    int gid  = lane >> 2, tg = lane & 3;
    int mt   = warp & 7;
    int nh   = warp >> 3;

    extern __shared__ unsigned psm[];
    unsigned* uph = psm;                // [256][72] proj hi
    unsigned* upl = psm + 256*72;       // [256][72] proj lo
    unsigned* uxh = psm + 2*256*72;     // [128][72] x hi
    unsigned* uxl = uxh + 128*72;       // [128][72] x lo
    __shared__ float diag_s[128];
    __shared__ float mx_s[128];
    __shared__ float red_s[256];

    for (int i = tid; i < MF*DH; i += 512) {
        int r = i >> 6, d = i & 63;
        float f = proj[i];
        unsigned hi = f2tf(f);
        uph[r*72 + d] = hi;
        upl[r*72 + d] = f2tf(f - __uint_as_float(hi));
    }

#pragma unroll
    for (int pass = 0; pass < 2; pass++) {
        const float* x = (pass == 0) ? q : k;
        const float* xb = x + ((size_t)head*NSEQ + t0)*DH;
        __syncthreads();
        for (int i = tid; i < 128*DH; i += 512) {
            int r = i >> 6, d = i & 63;
            float f = NORMALIZER * xb[i];
            unsigned hi = f2tf(f);
            uxh[r*72 + d] = hi;
            uxl[r*72 + d] = f2tf(f - __uint_as_float(hi));
        }
        __syncthreads();
        if (tid < 128) {
            float s = 0.f;
#pragma unroll 8
            for (int d = 0; d < DH; d++) {
                float vv = __uint_as_float(uxh[tid*72 + d]) + __uint_as_float(uxl[tid*72 + d]);
                s += vv*vv;
            }
            diag_s[tid] = 0.5f * s;
        }

        float acc[16][4];
#pragma unroll
        for (int j = 0; j < 16; j++)
#pragma unroll
            for (int r = 0; r < 4; r++) acc[j][r] = 0.f;

#pragma unroll
        for (int k0 = 0; k0 < DH; k0 += 8) {
            uint2 ah01 = *(const uint2*)&uxh[(mt*16 + gid    )*72 + k0 + 2*tg];
            uint2 ah23 = *(const uint2*)&uxh[(mt*16 + gid + 8)*72 + k0 + 2*tg];
            uint2 al01 = *(const uint2*)&uxl[(mt*16 + gid    )*72 + k0 + 2*tg];
            uint2 al23 = *(const uint2*)&uxl[(mt*16 + gid + 8)*72 + k0 + 2*tg];
#pragma unroll
            for (int jj = 0; jj < 16; jj++) {
                int row = (nh*16 + jj)*8 + gid;
                uint2 bh = *(const uint2*)&uph[row*72 + k0 + 2*tg];
                uint2 bl = *(const uint2*)&upl[row*72 + k0 + 2*tg];
                mma8(acc[jj], ah01.x, ah23.x, ah01.y, ah23.y, bh.x, bh.y);
                mma8(acc[jj], ah01.x, ah23.x, ah01.y, ah23.y, bl.x, bl.y);
                mma8(acc[jj], al01.x, al23.x, al01.y, al23.y, bh.x, bh.y);
            }
        }

        int row0 = mt*16 + gid, row1 = row0 + 8;
        if (pass == 0) {
            float m0 = -3.0e38f, m1 = -3.0e38f;
#pragma unroll
            for (int jj = 0; jj < 16; jj++) {
                m0 = fmaxf(m0, fmaxf(acc[jj][0], acc[jj][1]));
                m1 = fmaxf(m1, fmaxf(acc[jj][2], acc[jj][3]));
            }
            m0 = fmaxf(m0, __shfl_xor_sync(0xffffffffu, m0, 1));
            m0 = fmaxf(m0, __shfl_xor_sync(0xffffffffu, m0, 2));
            m1 = fmaxf(m1, __shfl_xor_sync(0xffffffffu, m1, 1));
            m1 = fmaxf(m1, __shfl_xor_sync(0xffffffffu, m1, 2));
            if (tg == 0) {
                red_s[nh*128 + row0] = m0;
                red_s[nh*128 + row1] = m1;
            }
            __syncthreads();
            if (tid < 128) mx_s[tid] = fmaxf(red_s[tid], red_s[128 + tid]);
            __syncthreads();
            float d0 = diag_s[row0] + mx_s[row0];
            float d1 = diag_s[row1] + mx_s[row1];
            unsigned* ob = (unsigned*)g_qp + ((size_t)head*NSEQ + t0)*MF;
#pragma unroll
            for (int jj = 0; jj < 16; jj++) {
                int f0 = (nh*16 + jj)*8 + 2*tg;
                uint2 w0 = make_uint2(f2tf(RATIO*(__expf(acc[jj][0] - d0) + EPSK)),
                                      f2tf(RATIO*(__expf(acc[jj][1] - d0) + EPSK)));
                uint2 w1 = make_uint2(f2tf(RATIO*(__expf(acc[jj][2] - d1) + EPSK)),
                                      f2tf(RATIO*(__expf(acc[jj][3] - d1) + EPSK)));
                *(uint2*)&ob[(size_t)row0*MF + f0] = w0;
                *(uint2*)&ob[(size_t)row1*MF + f0] = w1;
            }
        } else {
            float lm = -3.0e38f;
#pragma unroll
            for (int jj = 0; jj < 16; jj++) {
                lm = fmaxf(lm, fmaxf(fmaxf(acc[jj][0], acc[jj][1]),
                                     fmaxf(acc[jj][2], acc[jj][3])));
            }
#pragma unroll
            for (int o = 16; o >= 1; o >>= 1) lm = fmaxf(lm, __shfl_xor_sync(0xffffffffu, lm, o));
            if (lane == 0) red_s[warp] = lm;
            float d0 = diag_s[row0], d1 = diag_s[row1];
            float* ob = g_kp + ((size_t)head*NSEQ + t0)*MF;
#pragma unroll
            for (int jj = 0; jj < 16; jj++) {
                int f0 = (nh*16 + jj)*8 + 2*tg;
                *(float2*)&ob[(size_t)row0*MF + f0] = make_float2(acc[jj][0]-d0, acc[jj][1]-d0);
                *(float2*)&ob[(size_t)row1*MF + f0] = make_float2(acc[jj][2]-d1, acc[jj][3]-d1);
            }
            __syncthreads();
            if (tid == 0) {
                float mx = red_s[0];
                for (int r = 1; r < 16; r++) mx = fmaxf(mx, red_s[r]);
                atomicMaxF(&g_kmax[head], mx);
            }
        }
    }
}

// ---------------- chunksum: tf32 mma; writes phi(k) back as tf32 bits ----------------
__global__ __launch_bounds__(256) void chunksum_kernel(const float* __restrict__ v) {
    int head = blockIdx.x / NC, c = blockIdx.x % NC, t0 = c*CH, tid = threadIdx.x;
    extern __shared__ unsigned cs_u[];
    unsigned* uphi = cs_u;            // [256][72] tf32, [m][t]
    unsigned* uvT  = cs_u + 256*72;   // [64][72]  tf32, [d][t]

    const float* vb = v + ((size_t)head*NSEQ + t0)*DH;
    for (int i = tid; i < CH*DH; i += 256) {
        int t = i >> 6, d = i & 63;
        uvT[d*72 + t] = f2tf(vb[i]);
    }
    float kmax = g_kmax[head];
    float* kpb = g_kp + ((size_t)head*NSEQ + t0)*MF;
    for (int i = tid; i < CH*MF; i += 256) {
        int t = i >> 8, m = i & 255;
        float phi = RATIO * (__expf(kpb[i] - kmax) + EPSK);
        unsigned tb = f2tf(phi);
        kpb[i] = __uint_as_float(tb);
        uphi[m*72 + t] = tb;
    }
    __syncthreads();

    int lane = tid & 31, warp = tid >> 5, gid = lane >> 2, tg = lane & 3;
    int mt = warp >> 1, nh = warp & 1;

    float acc[16][4];
#pragma unroll
    for (int j = 0; j < 16; j++)
#pragma unroll
        for (int r = 0; r < 4; r++) acc[j][r] = 0.f;

#pragma unroll
    for (int k0 = 0; k0 < CH; k0 += 8) {
        uint2 a01 = *(const uint2*)&uvT[(mt*16 + gid    )*72 + k0 + 2*tg];
        uint2 a23 = *(const uint2*)&uvT[(mt*16 + gid + 8)*72 + k0 + 2*tg];
#pragma unroll
        for (int j = 0; j < 16; j++) {
            int m0 = (nh*16 + j)*8;
            uint2 bb = *(const uint2*)&uphi[(m0 + gid)*72 + k0 + 2*tg];
            mma8(acc[j], a01.x, a23.x, a01.y, a23.y, bb.x, bb.y);
        }
    }
    float* ob = g_csum + (size_t)(head*NC + c)*CSUM;
#pragma unroll
    for (int j = 0; j < 16; j++) {
        int m = (nh*16 + j)*8 + 2*tg;
        int d = mt*16 + gid;
        *(float2*)&ob[(size_t)d*MF + m]       = make_float2(acc[j][0], acc[j][1]);
        *(float2*)&ob[(size_t)(d + 8)*MF + m] = make_float2(acc[j][2], acc[j][3]);
    }
    if (tid < MF) {
        float s = 0.f;
#pragma unroll 8
        for (int tt = 0; tt < CH; tt++)
            s += __uint_as_float(uphi[tid*72 + (tt ^ (tid >> 2 & 7))]);
        ob[MF*DH + tid] = s;
    }
}

// Exclusive prefix over chunks. grid (BH, 65).
__global__ __launch_bounds__(256) void prefix_kernel() {
    int head = blockIdx.x;
    int idx  = blockIdx.y*256 + threadIdx.x;   // 65*256 = CSUM
    float* base = g_csum + (size_t)head*NC*CSUM + idx;
    float vals[NC];
#pragma unroll
    for (int cc = 0; cc < NC; cc++) vals[cc] = base[(size_t)cc*CSUM];
    float run = 0.f;
#pragma unroll
    for (int cc = 0; cc < NC; cc++) { base[(size_t)cc*CSUM] = run; run += vals[cc]; }
}

// ---------------- out: tf32 mma, 512 threads, private-accumulator tile split ----------------
__global__ __launch_bounds__(512) void out_kernel(const float* __restrict__ v,
                                                  float* __restrict__ out) {
    int head = blockIdx.x / NC, c = blockIdx.x % NC, t0 = c*CH, tid = threadIdx.x;
    extern __shared__ unsigned osm[];
    unsigned* uq  = osm;            // [64][264] tf32 Q'
    unsigned* upT = osm + 16896;    // [80][264] PT+spref row; aliases K' in phase 1
    unsigned* uvT = osm + 38016;    // [80][72]  VT + ones row
    unsigned* uS  = osm + 43776;    // [64][72]  masked S^T
    unsigned* uk  = upT;
    __shared__ float den_s[CH];

    // Q'/K' are tf32 bits in gmem -> pure 128-bit copies
    const uint4* qg4 = reinterpret_cast<const uint4*>(g_qp + ((size_t)head*NSEQ + t0)*MF);
    const uint4* kg4 = reinterpret_cast<const uint4*>(g_kp + ((size_t)head*NSEQ + t0)*MF);
    for (int i = tid; i < CH*MF/4; i += 512) {
        int t = i >> 6, m4 = (i & 63)*4;
        *(uint4*)&uq[t*264 + m4] = qg4[i];
        *(uint4*)&uk[t*264 + m4] = kg4[i];
    }
    const float* vb = v + ((size_t)head*NSEQ + t0)*DH;
    for (int i = tid; i < CH*DH; i += 512) {
        int t = i >> 6, d = i & 63;
        uvT[d*72 + t] = f2tf(vb[i]);
    }
    for (int i = tid; i < 16*72; i += 512) {
        int r = 64 + i/72, t = i % 72;
        uvT[r*72 + t] = (r == 64 && t < CH) ? 0x3f800000u : 0u;
    }
    __syncthreads();

    int lane = tid & 31, warp = tid >> 5, gid = lane >> 2, tg = lane & 3;

    // ---- phase 1: S^T over 16 warps (4 key-tiles x 4 q-quarters) ----
    {
        int kt = warp & 3;
        int qh = warp >> 2;
        float sacc[2][4];
#pragma unroll
        for (int j = 0; j < 2; j++)
#pragma unroll
            for (int r = 0; r < 4; r++) sacc[j][r] = 0.f;

#pragma unroll 4
        for (int k0 = 0; k0 < MF; k0 += 8) {
            uint2 a01 = *(const uint2*)&uk[(kt*16 + gid    )*264 + k0 + 2*tg];
            uint2 a23 = *(const uint2*)&uk[(kt*16 + gid + 8)*264 + k0 + 2*tg];
#pragma unroll
            for (int j = 0; j < 2; j++) {
                int q0 = qh*16 + j*8;
                uint2 bb = *(const uint2*)&uq[(q0 + gid)*264 + k0 + 2*tg];
                mma8(sacc[j], a01.x, a23.x, a01.y, a23.y, bb.x, bb.y);
            }
        }
#pragma unroll
        for (int j = 0; j < 2; j++) {
            int q0  = qh*16 + j*8 + 2*tg;
            int key = kt*16 + gid;
            unsigned m00 = (key     <= q0    ) ? f2tf(sacc[j][0]) : 0u;
            unsigned m01 = (key     <= q0 + 1) ? f2tf(sacc[j][1]) : 0u;
            unsigned m10 = (key + 8 <= q0    ) ? f2tf(sacc[j][2]) : 0u;
            unsigned m11 = (key + 8 <= q0 + 1) ? f2tf(sacc[j][3]) : 0u;
            *(uint2*)&uS[(key    )*72 + q0] = make_uint2(m00, m01);
            *(uint2*)&uS[(key + 8)*72 + q0] = make_uint2(m10, m11);
        }
    }
    __syncthreads();

    // stage P^T (+ spref+eps row 64, zeros 65..79); float4 -> uint4
    const float* pb = g_csum + (size_t)(head*NC + c)*CSUM;
    const float4* pb4 = reinterpret_cast<const float4*>(pb);
    for (int i = tid; i < MF*DH/4; i += 512) {
        int d = i >> 6, m4 = (i & 63)*4;
        float4 pv = pb4[i];
        *(uint4*)&upT[d*264 + m4] =
            make_uint4(f2tf(pv.x), f2tf(pv.y), f2tf(pv.z), f2tf(pv.w));
    }
    for (int m = tid; m < MF; m += 512) upT[64*264 + m] = f2tf(pb[MF*DH + m] + EPSD);
    for (int i = tid; i < 15*MF; i += 512) {
        int r = 65 + i/MF, m = i % MF;
        upT[r*264 + m] = 0u;
    }
    __syncthreads();

    // ---- phase 2: O^T = VT_ext@S^T + PT_ext@Q'^T, A-tiles split, private accumulators ----
    {
        int q0   = (warp & 7) * 8;
        int half = warp >> 3;          // 0: mt {0,1,2}; 1: mt {3,4}
        int mtb  = half ? 3 : 0;
        int nmt  = half ? 2 : 3;
        float co[3][4];
#pragma unroll
        for (int m = 0; m < 3; m++)
#pragma unroll
            for (int r = 0; r < 4; r++) co[m][r] = 0.f;

#pragma unroll
        for (int k0 = 0; k0 < CH; k0 += 8) {            // V.S term
            unsigned b0 = uS[(k0 + 2*tg    )*72 + q0 + gid];
            unsigned b1 = uS[(k0 + 2*tg + 1)*72 + q0 + gid];
            for (int m = 0; m < nmt; m++) {
                int mt = mtb + m;
                uint2 a01 = *(const uint2*)&uvT[(mt*16 + gid    )*72 + k0 + 2*tg];
                uint2 a23 = *(const uint2*)&uvT[(mt*16 + gid + 8)*72 + k0 + 2*tg];
                mma8(co[m], a01.x, a23.x, a01.y, a23.y, b0, b1);
            }
        }
#pragma unroll 4
        for (int k0 = 0; k0 < MF; k0 += 8) {            // P.Q term
            uint2 bb = *(const uint2*)&uq[(q0 + gid)*264 + k0 + 2*tg];
            for (int m = 0; m < nmt; m++) {
                int mt = mtb + m;
                uint2 a01 = *(const uint2*)&upT[(mt*16 + gid    )*264 + k0 + 2*tg];
                uint2 a23 = *(const uint2*)&upT[(mt*16 + gid + 8)*264 + k0 + 2*tg];
                mma8(co[m], a01.x, a23.x, a01.y, a23.y, bb.x, bb.y);
            }
        }

        // den = extended row 64 = tile mt4 (upper half, co[1]), local row 0 -> gid==0 lanes
        if (half && gid == 0) {
            den_s[q0 + 2*tg    ] = co[1][0];
            den_s[q0 + 2*tg + 1] = co[1][1];
        }
        __syncthreads();

        int qq = q0 + 2*tg;
        float i0 = 1.f / den_s[qq];
        float i1 = 1.f / den_s[qq + 1];
        float* ob = out + ((size_t)head*NSEQ + t0)*DH;
        int nst = half ? 1 : 3;        // upper half stores only mt 3 (mt4 is the den row)
        for (int m = 0; m < nst; m++) {
            int d = (mtb + m)*16 + gid;
            ob[(size_t)(qq    )*DH + d    ] = co[m][0]*i0;
            ob[(size_t)(qq + 1)*DH + d    ] = co[m][1]*i1;
            ob[(size_t)(qq    )*DH + d + 8] = co[m][2]*i0;
            ob[(size_t)(qq + 1)*DH + d + 8] = co[m][3]*i1;
        }
    }
}

extern "C" void kernel_launch(void* const* d_in, const int* in_sizes, int n_in,
                              void* d_out, int out_size) {
    const float* q    = (const float*)d_in[0];
    const float* k    = (const float*)d_in[1];
    const float* v    = (const float*)d_in[2];
    const float* proj = (const float*)d_in[3];
    float* out = (float*)d_out;

    size_t smem_pr  = (size_t)(2*256*72 + 2*128*72) * sizeof(unsigned);             // 221184
    size_t smem_cs  = (size_t)(256*72 + 64*72) * sizeof(unsigned);                  // 92160
    size_t smem_out = (size_t)(16896 + 21120 + 5760 + 4608) * sizeof(unsigned);     // 193536
    cudaFuncSetAttribute(proj_kernel,     cudaFuncAttributeMaxDynamicSharedMemorySize, (int)smem_pr);
    cudaFuncSetAttribute(chunksum_kernel, cudaFuncAttributeMaxDynamicSharedMemorySize, (int)smem_cs);
    cudaFuncSetAttribute(out_kernel,      cudaFuncAttributeMaxDynamicSharedMemorySize, (int)smem_out);

    init_kernel<<<1, 32>>>();
    proj_kernel<<<BH*16, 512, smem_pr>>>(q, k, proj);
    chunksum_kernel<<<BH*NC, 256, smem_cs>>>(v);
    prefix_kernel<<<dim3(BH, 65), 256>>>();
    out_kernel<<<BH*NC, 512, smem_out>>>(v, out);
}

// round 15
// speedup vs baseline: 1.6416x; 1.0428x over previous
#include <cuda_runtime.h>
#include <math.h>

#define BH   16
#define NSEQ 2048
#define DH   64
#define MF   256
#define CH   64
#define NC   (NSEQ/CH)
#define CSUM (MF*DH + MF)

#define NORMALIZER 0.35355339059327373f  // 64^-0.25
#define RATIO      0.0625f               // 256^-0.5
#define EPSK       1e-4f
#define EPSD       1e-6f

typedef unsigned long long ull;

__device__ __align__(16) float g_qp[BH*NSEQ*MF];   // phi(q) stored as tf32 BIT PATTERNS
__device__ __align__(16) float g_kp[BH*NSEQ*MF];   // xd-diag (fp32) -> phi(k) tf32 bits after chunksum
__device__ __align__(16) float g_kmax[BH];
__device__ __align__(16) float g_csum[BH*NC*CSUM]; // CtxT[d][m] + ksum[m] per chunk, exclusive-prefixed

__device__ __forceinline__ unsigned f2tf(float f) {
    unsigned u; asm("cvt.rna.tf32.f32 %0, %1;" : "=r"(u) : "f"(f)); return u;
}
__device__ __forceinline__ void mma8(float c[4], unsigned a0, unsigned a1,
                                     unsigned a2, unsigned a3,
                                     unsigned b0, unsigned b1) {
    asm("mma.sync.aligned.m16n8k8.row.col.f32.tf32.tf32.f32 "
        "{%0,%1,%2,%3},{%4,%5,%6,%7},{%8,%9},{%0,%1,%2,%3};"
        : "+f"(c[0]), "+f"(c[1]), "+f"(c[2]), "+f"(c[3])
        : "r"(a0), "r"(a1), "r"(a2), "r"(a3), "r"(b0), "r"(b1));
}
__device__ __forceinline__ ull pk2(float lo, float hi) {
    ull r; asm("mov.b64 %0, {%1,%2};" : "=l"(r) : "f"(lo), "f"(hi)); return r;
}

// Packed exp pair on the FMA pipe (frees MUFU). exp(a) = 2^(a*log2e),
// magic-constant round, deg-5 poly for 2^f (~2e-6 rel err), integer exponent
// insert. Valid for a in [-85, 0] with underflow clamp.
__device__ __forceinline__ void fexp2pair(float a0, float a1, float& r0, float& r1) {
    ull xx = pk2(a0, a1);
    ull tt; asm("mul.rn.f32x2 %0, %1, %2;" : "=l"(tt)
                : "l"(xx), "l"(pk2(1.4426950408889634f, 1.4426950408889634f)));
    ull zz; asm("add.rn.f32x2 %0, %1, %2;" : "=l"(zz)
                : "l"(tt), "l"(pk2(12582912.f, 12582912.f)));
    ull ww; asm("add.rn.f32x2 %0, %1, %2;" : "=l"(ww)
                : "l"(zz), "l"(pk2(-12582912.f, -12582912.f)));
    ull ff; asm("fma.rn.f32x2 %0, %1, %2, %3;" : "=l"(ff)
                : "l"(ww), "l"(pk2(-1.f, -1.f)), "l"(tt));
    ull p = pk2(1.3333558e-3f, 1.3333558e-3f);
    asm("fma.rn.f32x2 %0, %0, %1, %2;" : "+l"(p) : "l"(ff), "l"(pk2(9.6181291e-3f, 9.6181291e-3f)));
    asm("fma.rn.f32x2 %0, %0, %1, %2;" : "+l"(p) : "l"(ff), "l"(pk2(5.5504109e-2f, 5.5504109e-2f)));
    asm("fma.rn.f32x2 %0, %0, %1, %2;" : "+l"(p) : "l"(ff), "l"(pk2(2.4022651e-1f, 2.4022651e-1f)));
    asm("fma.rn.f32x2 %0, %0, %1, %2;" : "+l"(p) : "l"(ff), "l"(pk2(6.9314718e-1f, 6.9314718e-1f)));
    asm("fma.rn.f32x2 %0, %0, %1, %2;" : "+l"(p) : "l"(ff), "l"(pk2(1.0f, 1.0f)));
    unsigned z0, z1, p0, p1;
    asm("mov.b64 {%0,%1}, %2;" : "=r"(z0), "=r"(z1) : "l"(zz));
    asm("mov.b64 {%0,%1}, %2;" : "=r"(p0), "=r"(p1) : "l"(p));
    int n0 = max((int)z0, 0x4B400000 - 100);
    int n1 = max((int)z1, 0x4B400000 - 100);
    r0 = __int_as_float((int)p0 + (n0 << 23));
    r1 = __int_as_float((int)p1 + (n1 << 23));
}

__device__ __forceinline__ void atomicMaxF(float* addr, float val) {
    int old = __float_as_int(*addr);
    while (val > __int_as_float(old)) {
        int assumed = old;
        old = atomicCAS((int*)addr, assumed, __float_as_int(val));
        if (old == assumed) break;
    }
}

__global__ void init_kernel() {
    if (threadIdx.x < BH) g_kmax[threadIdx.x] = -3.0e38f;
}

// ---------------- fused proj: compensated tf32 mma, q + k passes ----------------
__global__ __launch_bounds__(512) void proj_kernel(const float* __restrict__ q,
                                                   const float* __restrict__ k,
                                                   const float* __restrict__ proj) {
    int head = blockIdx.x >> 4;
    int t0   = (blockIdx.x & 15) * 128;
    int tid  = threadIdx.x;
    int lane = tid & 31, warp = tid >> 5;
    int gid  = lane >> 2, tg = lane & 3;
    int mt   = warp & 7;
    int nh   = warp >> 3;

    extern __shared__ unsigned psm[];
    unsigned* uph = psm;                // [256][72] proj hi
    unsigned* upl = psm + 256*72;       // [256][72] proj lo
    unsigned* uxh = psm + 2*256*72;     // [128][72] x hi
    unsigned* uxl = uxh + 128*72;       // [128][72] x lo
    __shared__ float diag_s[128];
    __shared__ float mx_s[128];
    __shared__ float red_s[256];

    for (int i = tid; i < MF*DH; i += 512) {
        int r = i >> 6, d = i & 63;
        float f = proj[i];
        unsigned hi = f2tf(f);
        uph[r*72 + d] = hi;
        upl[r*72 + d] = f2tf(f - __uint_as_float(hi));
    }

#pragma unroll
    for (int pass = 0; pass < 2; pass++) {
        const float* x = (pass == 0) ? q : k;
        const float* xb = x + ((size_t)head*NSEQ + t0)*DH;
        __syncthreads();
        for (int i = tid; i < 128*DH; i += 512) {
            int r = i >> 6, d = i & 63;
            float f = NORMALIZER * xb[i];
            unsigned hi = f2tf(f);
            uxh[r*72 + d] = hi;
            uxl[r*72 + d] = f2tf(f - __uint_as_float(hi));
        }
        __syncthreads();
        if (tid < 128) {
            float s = 0.f;
#pragma unroll 8
            for (int d = 0; d < DH; d++) {
                float vv = __uint_as_float(uxh[tid*72 + d]) + __uint_as_float(uxl[tid*72 + d]);
                s += vv*vv;
            }
            diag_s[tid] = 0.5f * s;
        }

        float acc[16][4];
#pragma unroll
        for (int j = 0; j < 16; j++)
#pragma unroll
            for (int r = 0; r < 4; r++) acc[j][r] = 0.f;

#pragma unroll
        for (int k0 = 0; k0 < DH; k0 += 8) {
            uint2 ah01 = *(const uint2*)&uxh[(mt*16 + gid    )*72 + k0 + 2*tg];
            uint2 ah23 = *(const uint2*)&uxh[(mt*16 + gid + 8)*72 + k0 + 2*tg];
            uint2 al01 = *(const uint2*)&uxl[(mt*16 + gid    )*72 + k0 + 2*tg];
            uint2 al23 = *(const uint2*)&uxl[(mt*16 + gid + 8)*72 + k0 + 2*tg];
#pragma unroll
            for (int jj = 0; jj < 16; jj++) {
                int row = (nh*16 + jj)*8 + gid;
                uint2 bh = *(const uint2*)&uph[row*72 + k0 + 2*tg];
                uint2 bl = *(const uint2*)&upl[row*72 + k0 + 2*tg];
                mma8(acc[jj], ah01.x, ah23.x, ah01.y, ah23.y, bh.x, bh.y);
                mma8(acc[jj], ah01.x, ah23.x, ah01.y, ah23.y, bl.x, bl.y);
                mma8(acc[jj], al01.x, al23.x, al01.y, al23.y, bh.x, bh.y);
            }
        }

        int row0 = mt*16 + gid, row1 = row0 + 8;
        if (pass == 0) {
            float m0 = -3.0e38f, m1 = -3.0e38f;
#pragma unroll
            for (int jj = 0; jj < 16; jj++) {
                m0 = fmaxf(m0, fmaxf(acc[jj][0], acc[jj][1]));
                m1 = fmaxf(m1, fmaxf(acc[jj][2], acc[jj][3]));
            }
            m0 = fmaxf(m0, __shfl_xor_sync(0xffffffffu, m0, 1));
            m0 = fmaxf(m0, __shfl_xor_sync(0xffffffffu, m0, 2));
            m1 = fmaxf(m1, __shfl_xor_sync(0xffffffffu, m1, 1));
            m1 = fmaxf(m1, __shfl_xor_sync(0xffffffffu, m1, 2));
            if (tg == 0) {
                red_s[nh*128 + row0] = m0;
                red_s[nh*128 + row1] = m1;
            }
            __syncthreads();
            if (tid < 128) mx_s[tid] = fmaxf(red_s[tid], red_s[128 + tid]);
            __syncthreads();
            float d0 = diag_s[row0] + mx_s[row0];
            float d1 = diag_s[row1] + mx_s[row1];
            unsigned* ob = (unsigned*)g_qp + ((size_t)head*NSEQ + t0)*MF;
#pragma unroll
            for (int jj = 0; jj < 16; jj++) {
                int f0 = (nh*16 + jj)*8 + 2*tg;
                float e0, e1;
                fexp2pair(acc[jj][0] - d0, acc[jj][1] - d0, e0, e1);   // FMA pipe
                float e2 = __expf(acc[jj][2] - d1);                    // MUFU pipe
                float e3 = __expf(acc[jj][3] - d1);
                uint2 w0 = make_uint2(f2tf(RATIO*(e0 + EPSK)), f2tf(RATIO*(e1 + EPSK)));
                uint2 w1 = make_uint2(f2tf(RATIO*(e2 + EPSK)), f2tf(RATIO*(e3 + EPSK)));
                *(uint2*)&ob[(size_t)row0*MF + f0] = w0;
                *(uint2*)&ob[(size_t)row1*MF + f0] = w1;
            }
        } else {
            float lm = -3.0e38f;
#pragma unroll
            for (int jj = 0; jj < 16; jj++) {
                lm = fmaxf(lm, fmaxf(fmaxf(acc[jj][0], acc[jj][1]),
                                     fmaxf(acc[jj][2], acc[jj][3])));
            }
#pragma unroll
            for (int o = 16; o >= 1; o >>= 1) lm = fmaxf(lm, __shfl_xor_sync(0xffffffffu, lm, o));
            if (lane == 0) red_s[warp] = lm;
            float d0 = diag_s[row0], d1 = diag_s[row1];
            float* ob = g_kp + ((size_t)head*NSEQ + t0)*MF;
#pragma unroll
            for (int jj = 0; jj < 16; jj++) {
                int f0 = (nh*16 + jj)*8 + 2*tg;
                *(float2*)&ob[(size_t)row0*MF + f0] = make_float2(acc[jj][0]-d0, acc[jj][1]-d0);
                *(float2*)&ob[(size_t)row1*MF + f0] = make_float2(acc[jj][2]-d1, acc[jj][3]-d1);
            }
            __syncthreads();
            if (tid == 0) {
                float mx = red_s[0];
                for (int r = 1; r < 16; r++) mx = fmaxf(mx, red_s[r]);
                atomicMaxF(&g_kmax[head], mx);
            }
        }
    }
}

// ---------------- chunksum: tf32 mma; dual-pipe exp; phi(k) back as tf32 bits ----------------
__global__ __launch_bounds__(256) void chunksum_kernel(const float* __restrict__ v) {
    int head = blockIdx.x / NC, c = blockIdx.x % NC, t0 = c*CH, tid = threadIdx.x;
    extern __shared__ unsigned cs_u[];
    unsigned* uphi = cs_u;            // [256][72] tf32, [m][t]
    unsigned* uvT  = cs_u + 256*72;   // [64][72]  tf32, [d][t]

    const float* vb = v + ((size_t)head*NSEQ + t0)*DH;
    for (int i = tid; i < CH*DH; i += 256) {
        int t = i >> 6, d = i & 63;
        uvT[d*72 + t] = f2tf(vb[i]);
    }
    float kmax = g_kmax[head];
    float* kpb = g_kp + ((size_t)head*NSEQ + t0)*MF;
    // per thread: m = tid fixed, t = 0..63. 2 poly + 2 MUFU per group of 4.
#pragma unroll
    for (int it = 0; it < CH; it += 4) {
        float r0 = kpb[tid + (it    )*256];
        float r1 = kpb[tid + (it + 1)*256];
        float r2 = kpb[tid + (it + 2)*256];
        float r3 = kpb[tid + (it + 3)*256];
        float e0, e1;
        fexp2pair(r0 - kmax, r1 - kmax, e0, e1);   // FMA pipe
        float e2 = __expf(r2 - kmax);              // MUFU pipe
        float e3 = __expf(r3 - kmax);
        unsigned t0b = f2tf(RATIO*(e0 + EPSK));
        unsigned t1b = f2tf(RATIO*(e1 + EPSK));
        unsigned t2b = f2tf(RATIO*(e2 + EPSK));
        unsigned t3b = f2tf(RATIO*(e3 + EPSK));
        kpb[tid + (it    )*256] = __uint_as_float(t0b);
        kpb[tid + (it + 1)*256] = __uint_as_float(t1b);
        kpb[tid + (it + 2)*256] = __uint_as_float(t2b);
        kpb[tid + (it + 3)*256] = __uint_as_float(t3b);
        uphi[tid*72 + it    ] = t0b;
        uphi[tid*72 + it + 1] = t1b;
        uphi[tid*72 + it + 2] = t2b;
        uphi[tid*72 + it + 3] = t3b;
    }
    __syncthreads();

    int lane = tid & 31, warp = tid >> 5, gid = lane >> 2, tg = lane & 3;
    int mt = warp >> 1, nh = warp & 1;

    float acc[16][4];
#pragma unroll
    for (int j = 0; j < 16; j++)
#pragma unroll
        for (int r = 0; r < 4; r++) acc[j][r] = 0.f;

#pragma unroll
    for (int k0 = 0; k0 < CH; k0 += 8) {
        uint2 a01 = *(const uint2*)&uvT[(mt*16 + gid    )*72 + k0 + 2*tg];
        uint2 a23 = *(const uint2*)&uvT[(mt*16 + gid + 8)*72 + k0 + 2*tg];
#pragma unroll
        for (int j = 0; j < 16; j++) {
            int m0 = (nh*16 + j)*8;
            uint2 bb = *(const uint2*)&uphi[(m0 + gid)*72 + k0 + 2*tg];
            mma8(acc[j], a01.x, a23.x, a01.y, a23.y, bb.x, bb.y);
        }
    }
    float* ob = g_csum + (size_t)(head*NC + c)*CSUM;
#pragma unroll
    for (int j = 0; j < 16; j++) {
        int m = (nh*16 + j)*8 + 2*tg;
        int d = mt*16 + gid;
        *(float2*)&ob[(size_t)d*MF + m]       = make_float2(acc[j][0], acc[j][1]);
        *(float2*)&ob[(size_t)(d + 8)*MF + m] = make_float2(acc[j][2], acc[j][3]);
    }
    if (tid < MF) {
        float s = 0.f;
#pragma unroll 8
        for (int tt = 0; tt < CH; tt++)
            s += __uint_as_float(uphi[tid*72 + (tt ^ (tid >> 2 & 7))]);
        ob[MF*DH + tid] = s;
    }
}

// Exclusive prefix over chunks. grid (BH, 65).
__global__ __launch_bounds__(256) void prefix_kernel() {
    int head = blockIdx.x;
    int idx  = blockIdx.y*256 + threadIdx.x;   // 65*256 = CSUM
    float* base = g_csum + (size_t)head*NC*CSUM + idx;
    float vals[NC];
#pragma unroll
    for (int cc = 0; cc < NC; cc++) vals[cc] = base[(size_t)cc*CSUM];
    float run = 0.f;
#pragma unroll
    for (int cc = 0; cc < NC; cc++) { base[(size_t)cc*CSUM] = run; run += vals[cc]; }
}

// ---------------- out: tf32 mma, 512 threads, private-accumulator tile split ----------------
__global__ __launch_bounds__(512) void out_kernel(const float* __restrict__ v,
                                                  float* __restrict__ out) {
    int head = blockIdx.x / NC, c = blockIdx.x % NC, t0 = c*CH, tid = threadIdx.x;
    extern __shared__ unsigned osm[];
    unsigned* uq  = osm;            // [64][264] tf32 Q'
    unsigned* upT = osm + 16896;    // [80][264] PT+spref row; aliases K' in phase 1
    unsigned* uvT = osm + 38016;    // [80][72]  VT + ones row
    unsigned* uS  = osm + 43776;    // [64][72]  masked S^T
    unsigned* uk  = upT;
    __shared__ float den_s[CH];

    const uint4* qg4 = reinterpret_cast<const uint4*>(g_qp + ((size_t)head*NSEQ + t0)*MF);
    const uint4* kg4 = reinterpret_cast<const uint4*>(g_kp + ((size_t)head*NSEQ + t0)*MF);
    for (int i = tid; i < CH*MF/4; i += 512) {
        int t = i >> 6, m4 = (i & 63)*4;
        *(uint4*)&uq[t*264 + m4] = qg4[i];
        *(uint4*)&uk[t*264 + m4] = kg4[i];
    }
    const float* vb = v + ((size_t)head*NSEQ + t0)*DH;
    for (int i = tid; i < CH*DH; i += 512) {
        int t = i >> 6, d = i & 63;
        uvT[d*72 + t] = f2tf(vb[i]);
    }
    for (int i = tid; i < 16*72; i += 512) {
        int r = 64 + i/72, t = i % 72;
        uvT[r*72 + t] = (r == 64 && t < CH) ? 0x3f800000u : 0u;
    }
    __syncthreads();

    int lane = tid & 31, warp = tid >> 5, gid = lane >> 2, tg = lane & 3;

    // ---- phase 1: S^T over 16 warps (4 key-tiles x 4 q-quarters) ----
    {
        int kt = warp & 3;
        int qh = warp >> 2;
        float sacc[2][4];
#pragma unroll
        for (int j = 0; j < 2; j++)
#pragma unroll
            for (int r = 0; r < 4; r++) sacc[j][r] = 0.f;

#pragma unroll 4
        for (int k0 = 0; k0 < MF; k0 += 8) {
            uint2 a01 = *(const uint2*)&uk[(kt*16 + gid    )*264 + k0 + 2*tg];
            uint2 a23 = *(const uint2*)&uk[(kt*16 + gid + 8)*264 + k0 + 2*tg];
#pragma unroll
            for (int j = 0; j < 2; j++) {
                int q0 = qh*16 + j*8;
                uint2 bb = *(const uint2*)&uq[(q0 + gid)*264 + k0 + 2*tg];
                mma8(sacc[j], a01.x, a23.x, a01.y, a23.y, bb.x, bb.y);
            }
        }
#pragma unroll
        for (int j = 0; j < 2; j++) {
            int q0  = qh*16 + j*8 + 2*tg;
            int key = kt*16 + gid;
            unsigned m00 = (key     <= q0    ) ? f2tf(sacc[j][0]) : 0u;
            unsigned m01 = (key     <= q0 + 1) ? f2tf(sacc[j][1]) : 0u;
            unsigned m10 = (key + 8 <= q0    ) ? f2tf(sacc[j][2]) : 0u;
            unsigned m11 = (key + 8 <= q0 + 1) ? f2tf(sacc[j][3]) : 0u;
            *(uint2*)&uS[(key    )*72 + q0] = make_uint2(m00, m01);
            *(uint2*)&uS[(key + 8)*72 + q0] = make_uint2(m10, m11);
        }
    }
    __syncthreads();

    const float* pb = g_csum + (size_t)(head*NC + c)*CSUM;
    const float4* pb4 = reinterpret_cast<const float4*>(pb);
    for (int i = tid; i < MF*DH/4; i += 512) {
        int d = i >> 6, m4 = (i & 63)*4;
        float4 pv = pb4[i];
        *(uint4*)&upT[d*264 + m4] =
            make_uint4(f2tf(pv.x), f2tf(pv.y), f2tf(pv.z), f2tf(pv.w));
    }
    for (int m = tid; m < MF; m += 512) upT[64*264 + m] = f2tf(pb[MF*DH + m] + EPSD);
    for (int i = tid; i < 15*MF; i += 512) {
        int r = 65 + i/MF, m = i % MF;
        upT[r*264 + m] = 0u;
    }
    __syncthreads();

    // ---- phase 2: A-tiles split, private accumulators ----
    {
        int q0   = (warp & 7) * 8;
        int half = warp >> 3;          // 0: mt {0,1,2}; 1: mt {3,4}
        int mtb  = half ? 3 : 0;
        int nmt  = half ? 2 : 3;
        float co[3][4];
#pragma unroll
        for (int m = 0; m < 3; m++)
#pragma unroll
            for (int r = 0; r < 4; r++) co[m][r] = 0.f;

#pragma unroll
        for (int k0 = 0; k0 < CH; k0 += 8) {            // V.S term
            unsigned b0 = uS[(k0 + 2*tg    )*72 + q0 + gid];
            unsigned b1 = uS[(k0 + 2*tg + 1)*72 + q0 + gid];
            for (int m = 0; m < nmt; m++) {
                int mt = mtb + m;
                uint2 a01 = *(const uint2*)&uvT[(mt*16 + gid    )*72 + k0 + 2*tg];
                uint2 a23 = *(const uint2*)&uvT[(mt*16 + gid + 8)*72 + k0 + 2*tg];
                mma8(co[m], a01.x, a23.x, a01.y, a23.y, b0, b1);
            }
        }
#pragma unroll 4
        for (int k0 = 0; k0 < MF; k0 += 8) {            // P.Q term
            uint2 bb = *(const uint2*)&uq[(q0 + gid)*264 + k0 + 2*tg];
            for (int m = 0; m < nmt; m++) {
                int mt = mtb + m;
                uint2 a01 = *(const uint2*)&upT[(mt*16 + gid    )*264 + k0 + 2*tg];
                uint2 a23 = *(const uint2*)&upT[(mt*16 + gid + 8)*264 + k0 + 2*tg];
                mma8(co[m], a01.x, a23.x, a01.y, a23.y, bb.x, bb.y);
            }
        }

        if (half && gid == 0) {
            den_s[q0 + 2*tg    ] = co[1][0];
            den_s[q0 + 2*tg + 1] = co[1][1];
        }
        __syncthreads();

        int qq = q0 + 2*tg;
        float i0 = 1.f / den_s[qq];
        float i1 = 1.f / den_s[qq + 1];
        float* ob = out + ((size_t)head*NSEQ + t0)*DH;
        int nst = half ? 1 : 3;
        for (int m = 0; m < nst; m++) {
            int d = (mtb + m)*16 + gid;
            ob[(size_t)(qq    )*DH + d    ] = co[m][0]*i0;
            ob[(size_t)(qq + 1)*DH + d    ] = co[m][1]*i1;
            ob[(size_t)(qq    )*DH + d + 8] = co[m][2]*i0;
            ob[(size_t)(qq + 1)*DH + d + 8] = co[m][3]*i1;
        }
    }
}

extern "C" void kernel_launch(void* const* d_in, const int* in_sizes, int n_in,
                              void* d_out, int out_size) {
    const float* q    = (const float*)d_in[0];
    const float* k    = (const float*)d_in[1];
    const float* v    = (const float*)d_in[2];
    const float* proj = (const float*)d_in[3];
    float* out = (float*)d_out;

    size_t smem_pr  = (size_t)(2*256*72 + 2*128*72) * sizeof(unsigned);             // 221184
    size_t smem_cs  = (size_t)(256*72 + 64*72) * sizeof(unsigned);                  // 92160
    size_t smem_out = (size_t)(16896 + 21120 + 5760 + 4608) * sizeof(unsigned);     // 193536
    cudaFuncSetAttribute(proj_kernel,     cudaFuncAttributeMaxDynamicSharedMemorySize, (int)smem_pr);
    cudaFuncSetAttribute(chunksum_kernel, cudaFuncAttributeMaxDynamicSharedMemorySize, (int)smem_cs);
    cudaFuncSetAttribute(out_kernel,      cudaFuncAttributeMaxDynamicSharedMemorySize, (int)smem_out);

    init_kernel<<<1, 32>>>();
    proj_kernel<<<BH*16, 512, smem_pr>>>(q, k, proj);
    chunksum_kernel<<<BH*NC, 256, smem_cs>>>(v);
    prefix_kernel<<<dim3(BH, 65), 256>>>();
    out_kernel<<<BH*NC, 512, smem_out>>>(v, out);
}

// round 17
// speedup vs baseline: 1.6997x; 1.0354x over previous
#include <cuda_runtime.h>
#include <math.h>

#define BH   16
#define NSEQ 2048
#define DH   64
#define MF   256
#define CH   64
#define NC   (NSEQ/CH)
#define CSUM (MF*DH + MF)

#define NORMALIZER 0.35355339059327373f  // 64^-0.25
#define RATIO      0.0625f               // 256^-0.5
#define EPSK       1e-4f
#define EPSD       1e-6f

typedef unsigned long long ull;

__device__ __align__(16) float g_qp[BH*NSEQ*MF];   // phi(q) stored as tf32 BIT PATTERNS
__device__ __align__(16) float g_kp[BH*NSEQ*MF];   // xd-diag (fp32) -> phi(k) tf32 bits after chunksum
__device__ __align__(16) float g_kmax[BH];
__device__ __align__(16) float g_csum[BH*NC*CSUM]; // CtxT[d][m] + ksum[m] per chunk, exclusive-prefixed

__device__ __forceinline__ unsigned f2tf(float f) {
    unsigned u; asm("cvt.rna.tf32.f32 %0, %1;" : "=r"(u) : "f"(f)); return u;
}
__device__ __forceinline__ void mma8(float c[4], unsigned a0, unsigned a1,
                                     unsigned a2, unsigned a3,
                                     unsigned b0, unsigned b1) {
    asm("mma.sync.aligned.m16n8k8.row.col.f32.tf32.tf32.f32 "
        "{%0,%1,%2,%3},{%4,%5,%6,%7},{%8,%9},{%0,%1,%2,%3};"
        : "+f"(c[0]), "+f"(c[1]), "+f"(c[2]), "+f"(c[3])
        : "r"(a0), "r"(a1), "r"(a2), "r"(a3), "r"(b0), "r"(b1));
}
__device__ __forceinline__ ull pk2(float lo, float hi) {
    ull r; asm("mov.b64 %0, {%1,%2};" : "=l"(r) : "f"(lo), "f"(hi)); return r;
}

// Packed exp pair on the FMA pipe (frees MUFU). exp(a) = 2^(a*log2e),
// magic-constant round, deg-5 poly for 2^f (~2e-6 rel err), integer exponent
// insert. Valid for a in [-85, 0] with underflow clamp.
__device__ __forceinline__ void fexp2pair(float a0, float a1, float& r0, float& r1) {
    ull xx = pk2(a0, a1);
    ull tt; asm("mul.rn.f32x2 %0, %1, %2;" : "=l"(tt)
                : "l"(xx), "l"(pk2(1.4426950408889634f, 1.4426950408889634f)));
    ull zz; asm("add.rn.f32x2 %0, %1, %2;" : "=l"(zz)
                : "l"(tt), "l"(pk2(12582912.f, 12582912.f)));
    ull ww; asm("add.rn.f32x2 %0, %1, %2;" : "=l"(ww)
                : "l"(zz), "l"(pk2(-12582912.f, -12582912.f)));
    ull ff; asm("fma.rn.f32x2 %0, %1, %2, %3;" : "=l"(ff)
                : "l"(ww), "l"(pk2(-1.f, -1.f)), "l"(tt));
    ull p = pk2(1.3333558e-3f, 1.3333558e-3f);
    asm("fma.rn.f32x2 %0, %0, %1, %2;" : "+l"(p) : "l"(ff), "l"(pk2(9.6181291e-3f, 9.6181291e-3f)));
    asm("fma.rn.f32x2 %0, %0, %1, %2;" : "+l"(p) : "l"(ff), "l"(pk2(5.5504109e-2f, 5.5504109e-2f)));
    asm("fma.rn.f32x2 %0, %0, %1, %2;" : "+l"(p) : "l"(ff), "l"(pk2(2.4022651e-1f, 2.4022651e-1f)));
    asm("fma.rn.f32x2 %0, %0, %1, %2;" : "+l"(p) : "l"(ff), "l"(pk2(6.9314718e-1f, 6.9314718e-1f)));
    asm("fma.rn.f32x2 %0, %0, %1, %2;" : "+l"(p) : "l"(ff), "l"(pk2(1.0f, 1.0f)));
    unsigned z0, z1, p0, p1;
    asm("mov.b64 {%0,%1}, %2;" : "=r"(z0), "=r"(z1) : "l"(zz));
    asm("mov.b64 {%0,%1}, %2;" : "=r"(p0), "=r"(p1) : "l"(p));
    int n0 = max((int)z0, 0x4B400000 - 100);
    int n1 = max((int)z1, 0x4B400000 - 100);
    r0 = __int_as_float((int)p0 + (n0 << 23));
    r1 = __int_as_float((int)p1 + (n1 << 23));
}

__device__ __forceinline__ void atomicMaxF(float* addr, float val) {
    int old = __float_as_int(*addr);
    while (val > __int_as_float(old)) {
        int assumed = old;
        old = atomicCAS((int*)addr, assumed, __float_as_int(val));
        if (old == assumed) break;
    }
}

__global__ void init_kernel() {
    if (threadIdx.x < BH) g_kmax[threadIdx.x] = -3.0e38f;
}

// ---------------- fused proj: compensated tf32 mma, q + k passes ----------------
__global__ __launch_bounds__(512) void proj_kernel(const float* __restrict__ q,
                                                   const float* __restrict__ k,
                                                   const float* __restrict__ proj) {
    int head = blockIdx.x >> 4;
    int t0   = (blockIdx.x & 15) * 128;
    int tid  = threadIdx.x;
    int lane = tid & 31, warp = tid >> 5;
    int gid  = lane >> 2, tg = lane & 3;
    int mt   = warp & 7;
    int nh   = warp >> 3;

    extern __shared__ unsigned psm[];
    unsigned* uph = psm;                // [256][72] proj hi
    unsigned* upl = psm + 256*72;       // [256][72] proj lo
    unsigned* uxh = psm + 2*256*72;     // [128][72] x hi
    unsigned* uxl = uxh + 128*72;       // [128][72] x lo
    __shared__ float diag_s[128];
    __shared__ float mx_s[128];
    __shared__ float red_s[256];

    for (int i = tid; i < MF*DH; i += 512) {
        int r = i >> 6, d = i & 63;
        float f = proj[i];
        unsigned hi = f2tf(f);
        uph[r*72 + d] = hi;
        upl[r*72 + d] = f2tf(f - __uint_as_float(hi));
    }

#pragma unroll
    for (int pass = 0; pass < 2; pass++) {
        const float* x = (pass == 0) ? q : k;
        const float* xb = x + ((size_t)head*NSEQ + t0)*DH;
        __syncthreads();
        for (int i = tid; i < 128*DH; i += 512) {
            int r = i >> 6, d = i & 63;
            float f = NORMALIZER * xb[i];
            unsigned hi = f2tf(f);
            uxh[r*72 + d] = hi;
            uxl[r*72 + d] = f2tf(f - __uint_as_float(hi));
        }
        __syncthreads();
        if (tid < 128) {
            float s = 0.f;
#pragma unroll 8
            for (int d = 0; d < DH; d++) {
                float vv = __uint_as_float(uxh[tid*72 + d]) + __uint_as_float(uxl[tid*72 + d]);
                s += vv*vv;
            }
            diag_s[tid] = 0.5f * s;
        }

        float acc[16][4];
#pragma unroll
        for (int j = 0; j < 16; j++)
#pragma unroll
            for (int r = 0; r < 4; r++) acc[j][r] = 0.f;

#pragma unroll
        for (int k0 = 0; k0 < DH; k0 += 8) {
            uint2 ah01 = *(const uint2*)&uxh[(mt*16 + gid    )*72 + k0 + 2*tg];
            uint2 ah23 = *(const uint2*)&uxh[(mt*16 + gid + 8)*72 + k0 + 2*tg];
            uint2 al01 = *(const uint2*)&uxl[(mt*16 + gid    )*72 + k0 + 2*tg];
            uint2 al23 = *(const uint2*)&uxl[(mt*16 + gid + 8)*72 + k0 + 2*tg];
#pragma unroll
            for (int jj = 0; jj < 16; jj++) {
                int row = (nh*16 + jj)*8 + gid;
                uint2 bh = *(const uint2*)&uph[row*72 + k0 + 2*tg];
                uint2 bl = *(const uint2*)&upl[row*72 + k0 + 2*tg];
                mma8(acc[jj], ah01.x, ah23.x, ah01.y, ah23.y, bh.x, bh.y);
                mma8(acc[jj], ah01.x, ah23.x, ah01.y, ah23.y, bl.x, bl.y);
                mma8(acc[jj], al01.x, al23.x, al01.y, al23.y, bh.x, bh.y);
            }
        }

        int row0 = mt*16 + gid, row1 = row0 + 8;
        if (pass == 0) {
            float m0 = -3.0e38f, m1 = -3.0e38f;
#pragma unroll
            for (int jj = 0; jj < 16; jj++) {
                m0 = fmaxf(m0, fmaxf(acc[jj][0], acc[jj][1]));
                m1 = fmaxf(m1, fmaxf(acc[jj][2], acc[jj][3]));
            }
            m0 = fmaxf(m0, __shfl_xor_sync(0xffffffffu, m0, 1));
            m0 = fmaxf(m0, __shfl_xor_sync(0xffffffffu, m0, 2));
            m1 = fmaxf(m1, __shfl_xor_sync(0xffffffffu, m1, 1));
            m1 = fmaxf(m1, __shfl_xor_sync(0xffffffffu, m1, 2));
            if (tg == 0) {
                red_s[nh*128 + row0] = m0;
                red_s[nh*128 + row1] = m1;
            }
            __syncthreads();
            if (tid < 128) mx_s[tid] = fmaxf(red_s[tid], red_s[128 + tid]);
            __syncthreads();
            float d0 = diag_s[row0] + mx_s[row0];
            float d1 = diag_s[row1] + mx_s[row1];
            unsigned* ob = (unsigned*)g_qp + ((size_t)head*NSEQ + t0)*MF;
#pragma unroll
            for (int jj = 0; jj < 16; jj++) {
                int f0 = (nh*16 + jj)*8 + 2*tg;
                float e0, e1;
                fexp2pair(acc[jj][0] - d0, acc[jj][1] - d0, e0, e1);   // FMA pipe
                float e2 = __expf(acc[jj][2] - d1);                    // MUFU pipe
                float e3 = __expf(acc[jj][3] - d1);
                uint2 w0 = make_uint2(f2tf(RATIO*(e0 + EPSK)), f2tf(RATIO*(e1 + EPSK)));
                uint2 w1 = make_uint2(f2tf(RATIO*(e2 + EPSK)), f2tf(RATIO*(e3 + EPSK)));
                *(uint2*)&ob[(size_t)row0*MF + f0] = w0;
                *(uint2*)&ob[(size_t)row1*MF + f0] = w1;
            }
        } else {
            float lm = -3.0e38f;
#pragma unroll
            for (int jj = 0; jj < 16; jj++) {
                lm = fmaxf(lm, fmaxf(fmaxf(acc[jj][0], acc[jj][1]),
                                     fmaxf(acc[jj][2], acc[jj][3])));
            }
#pragma unroll
            for (int o = 16; o >= 1; o >>= 1) lm = fmaxf(lm, __shfl_xor_sync(0xffffffffu, lm, o));
            if (lane == 0) red_s[warp] = lm;
            float d0 = diag_s[row0], d1 = diag_s[row1];
            float* ob = g_kp + ((size_t)head*NSEQ + t0)*MF;
#pragma unroll
            for (int jj = 0; jj < 16; jj++) {
                int f0 = (nh*16 + jj)*8 + 2*tg;
                *(float2*)&ob[(size_t)row0*MF + f0] = make_float2(acc[jj][0]-d0, acc[jj][1]-d0);
                *(float2*)&ob[(size_t)row1*MF + f0] = make_float2(acc[jj][2]-d1, acc[jj][3]-d1);
            }
            __syncthreads();
            if (tid == 0) {
                float mx = red_s[0];
                for (int r = 1; r < 16; r++) mx = fmaxf(mx, red_s[r]);
                atomicMaxF(&g_kmax[head], mx);
            }
        }
    }
}

// ---------------- chunksum: 512 threads, dual-pipe exp with 2x ILP, 16-warp mma ----------------
__global__ __launch_bounds__(512) void chunksum_kernel(const float* __restrict__ v) {
    int head = blockIdx.x / NC, c = blockIdx.x % NC, t0 = c*CH, tid = threadIdx.x;
    extern __shared__ unsigned cs_u[];
    unsigned* uphi = cs_u;                         // [256][72] tf32, [m][t]
    unsigned* uvT  = cs_u + 256*72;                // [64][72]  tf32, [d][t]
    float* psum    = (float*)(cs_u + 256*72 + 64*72);  // [512] partial ksums

    const float* vb = v + ((size_t)head*NSEQ + t0)*DH;
    for (int i = tid; i < CH*DH; i += 512) {
        int t = i >> 6, d = i & 63;
        uvT[d*72 + t] = f2tf(vb[i]);
    }
    float kmax = g_kmax[head];
    float* kpb = g_kp + ((size_t)head*NSEQ + t0)*MF;

    // exp phase: thread = (half, m); each handles 32 t-values. 2 poly + 2 MUFU per 4.
    int m  = tid & 255;
    int tb = (tid >> 8) * 32;
    float ps = 0.f;
#pragma unroll
    for (int it = 0; it < 32; it += 4) {
        int t = tb + it;
        float r0 = kpb[m + (t    )*256];
        float r1 = kpb[m + (t + 1)*256];
        float r2 = kpb[m + (t + 2)*256];
        float r3 = kpb[m + (t + 3)*256];
        float e0, e1;
        fexp2pair(r0 - kmax, r1 - kmax, e0, e1);   // FMA pipe
        float e2 = __expf(r2 - kmax);              // MUFU pipe
        float e3 = __expf(r3 - kmax);
        unsigned t0b = f2tf(RATIO*(e0 + EPSK));
        unsigned t1b = f2tf(RATIO*(e1 + EPSK));
        unsigned t2b = f2tf(RATIO*(e2 + EPSK));
        unsigned t3b = f2tf(RATIO*(e3 + EPSK));
        kpb[m + (t    )*256] = __uint_as_float(t0b);
        kpb[m + (t + 1)*256] = __uint_as_float(t1b);
        kpb[m + (t + 2)*256] = __uint_as_float(t2b);
        kpb[m + (t + 3)*256] = __uint_as_float(t3b);
        uphi[m*72 + t    ] = t0b;
        uphi[m*72 + t + 1] = t1b;
        uphi[m*72 + t + 2] = t2b;
        uphi[m*72 + t + 3] = t3b;
        ps += __uint_as_float(t0b); ps += __uint_as_float(t1b);
        ps += __uint_as_float(t2b); ps += __uint_as_float(t3b);
    }
    psum[tid] = ps;
    __syncthreads();

    // mma phase: 16 warps = 4 d-tiles x 4 feature-quarters, acc[8][4]
    int lane = tid & 31, warp = tid >> 5, gid = lane >> 2, tg = lane & 3;
    int mt = warp & 3, nq = warp >> 2;

    float acc[8][4];
#pragma unroll
    for (int j = 0; j < 8; j++)
#pragma unroll
        for (int r = 0; r < 4; r++) acc[j][r] = 0.f;

#pragma unroll
    for (int k0 = 0; k0 < CH; k0 += 8) {
        uint2 a01 = *(const uint2*)&uvT[(mt*16 + gid    )*72 + k0 + 2*tg];
        uint2 a23 = *(const uint2*)&uvT[(mt*16 + gid + 8)*72 + k0 + 2*tg];
#pragma unroll
        for (int j = 0; j < 8; j++) {
            int m0 = (nq*8 + j)*8;
            uint2 bb = *(const uint2*)&uphi[(m0 + gid)*72 + k0 + 2*tg];
            mma8(acc[j], a01.x, a23.x, a01.y, a23.y, bb.x, bb.y);
        }
    }
    float* ob = g_csum + (size_t)(head*NC + c)*CSUM;
#pragma unroll
    for (int j = 0; j < 8; j++) {
        int mm = (nq*8 + j)*8 + 2*tg;
        int d  = mt*16 + gid;
        *(float2*)&ob[(size_t)d*MF + mm]       = make_float2(acc[j][0], acc[j][1]);
        *(float2*)&ob[(size_t)(d + 8)*MF + mm] = make_float2(acc[j][2], acc[j][3]);
    }
    if (tid < MF) ob[MF*DH + tid] = psum[tid] + psum[tid + 256];
}

// Exclusive prefix over chunks. grid (BH, 65).
__global__ __launch_bounds__(256) void prefix_kernel() {
    int head = blockIdx.x;
    int idx  = blockIdx.y*256 + threadIdx.x;   // 65*256 = CSUM
    float* base = g_csum + (size_t)head*NC*CSUM + idx;
    float vals[NC];
#pragma unroll
    for (int cc = 0; cc < NC; cc++) vals[cc] = base[(size_t)cc*CSUM];
    float run = 0.f;
#pragma unroll
    for (int cc = 0; cc < NC; cc++) { base[(size_t)cc*CSUM] = run; run += vals[cc]; }
}

// ---------------- out: tf32 mma, 512 threads, private-accumulator tile split ----------------
__global__ __launch_bounds__(512) void out_kernel(const float* __restrict__ v,
                                                  float* __restrict__ out) {
    int head = blockIdx.x / NC, c = blockIdx.x % NC, t0 = c*CH, tid = threadIdx.x;
    extern __shared__ unsigned osm[];
    unsigned* uq  = osm;            // [64][264] tf32 Q'
    unsigned* upT = osm + 16896;    // [80][264] PT+spref row; aliases K' in phase 1
    unsigned* uvT = osm + 38016;    // [80][72]  VT + ones row
    unsigned* uS  = osm + 43776;    // [64][72]  masked S^T
    unsigned* uk  = upT;
    __shared__ float den_s[CH];

    const uint4* qg4 = reinterpret_cast<const uint4*>(g_qp + ((size_t)head*NSEQ + t0)*MF);
    const uint4* kg4 = reinterpret_cast<const uint4*>(g_kp + ((size_t)head*NSEQ + t0)*MF);
    for (int i = tid; i < CH*MF/4; i += 512) {
        int t = i >> 6, m4 = (i & 63)*4;
        *(uint4*)&uq[t*264 + m4] = qg4[i];
        *(uint4*)&uk[t*264 + m4] = kg4[i];
    }
    const float* vb = v + ((size_t)head*NSEQ + t0)*DH;
    for (int i = tid; i < CH*DH; i += 512) {
        int t = i >> 6, d = i & 63;
        uvT[d*72 + t] = f2tf(vb[i]);
    }
    for (int i = tid; i < 16*72; i += 512) {
        int r = 64 + i/72, t = i % 72;
        uvT[r*72 + t] = (r == 64 && t < CH) ? 0x3f800000u : 0u;
    }
    __syncthreads();

    int lane = tid & 31, warp = tid >> 5, gid = lane >> 2, tg = lane & 3;

    // ---- phase 1: S^T over 16 warps (4 key-tiles x 4 q-quarters) ----
    {
        int kt = warp & 3;
        int qh = warp >> 2;
        float sacc[2][4];
#pragma unroll
        for (int j = 0; j < 2; j++)
#pragma unroll
            for (int r = 0; r < 4; r++) sacc[j][r] = 0.f;

#pragma unroll 4
        for (int k0 = 0; k0 < MF; k0 += 8) {
            uint2 a01 = *(const uint2*)&uk[(kt*16 + gid    )*264 + k0 + 2*tg];
            uint2 a23 = *(const uint2*)&uk[(kt*16 + gid + 8)*264 + k0 + 2*tg];
#pragma unroll
            for (int j = 0; j < 2; j++) {
                int q0 = qh*16 + j*8;
                uint2 bb = *(const uint2*)&uq[(q0 + gid)*264 + k0 + 2*tg];
                mma8(sacc[j], a01.x, a23.x, a01.y, a23.y, bb.x, bb.y);
            }
        }
#pragma unroll
        for (int j = 0; j < 2; j++) {
            int q0  = qh*16 + j*8 + 2*tg;
            int key = kt*16 + gid;
            unsigned m00 = (key     <= q0    ) ? f2tf(sacc[j][0]) : 0u;
            unsigned m01 = (key     <= q0 + 1) ? f2tf(sacc[j][1]) : 0u;
            unsigned m10 = (key + 8 <= q0    ) ? f2tf(sacc[j][2]) : 0u;
            unsigned m11 = (key + 8 <= q0 + 1) ? f2tf(sacc[j][3]) : 0u;
            *(uint2*)&uS[(key    )*72 + q0] = make_uint2(m00, m01);
            *(uint2*)&uS[(key + 8)*72 + q0] = make_uint2(m10, m11);
        }
    }
    __syncthreads();

    const float* pb = g_csum + (size_t)(head*NC + c)*CSUM;
    const float4* pb4 = reinterpret_cast<const float4*>(pb);
    for (int i = tid; i < MF*DH/4; i += 512) {
        int d = i >> 6, m4 = (i & 63)*4;
        float4 pv = pb4[i];
        *(uint4*)&upT[d*264 + m4] =
            make_uint4(f2tf(pv.x), f2tf(pv.y), f2tf(pv.z), f2tf(pv.w));
    }
    for (int m = tid; m < MF; m += 512) upT[64*264 + m] = f2tf(pb[MF*DH + m] + EPSD);
    for (int i = tid; i < 15*MF; i += 512) {
        int r = 65 + i/MF, m = i % MF;
        upT[r*264 + m] = 0u;
    }
    __syncthreads();

    // ---- phase 2: A-tiles split, private accumulators ----
    {
        int q0   = (warp & 7) * 8;
        int half = warp >> 3;          // 0: mt {0,1,2}; 1: mt {3,4}
        int mtb  = half ? 3 : 0;
        int nmt  = half ? 2 : 3;
        float co[3][4];
#pragma unroll
        for (int m = 0; m < 3; m++)
#pragma unroll
            for (int r = 0; r < 4; r++) co[m][r] = 0.f;

#pragma unroll
        for (int k0 = 0; k0 < CH; k0 += 8) {            // V.S term
            unsigned b0 = uS[(k0 + 2*tg    )*72 + q0 + gid];
            unsigned b1 = uS[(k0 + 2*tg + 1)*72 + q0 + gid];
            for (int m = 0; m < nmt; m++) {
                int mt = mtb + m;
                uint2 a01 = *(const uint2*)&uvT[(mt*16 + gid    )*72 + k0 + 2*tg];
                uint2 a23 = *(const uint2*)&uvT[(mt*16 + gid + 8)*72 + k0 + 2*tg];
                mma8(co[m], a01.x, a23.x, a01.y, a23.y, b0, b1);
            }
        }
#pragma unroll 4
        for (int k0 = 0; k0 < MF; k0 += 8) {            // P.Q term
            uint2 bb = *(const uint2*)&uq[(q0 + gid)*264 + k0 + 2*tg];
            for (int m = 0; m < nmt; m++) {
                int mt = mtb + m;
                uint2 a01 = *(const uint2*)&upT[(mt*16 + gid    )*264 + k0 + 2*tg];
                uint2 a23 = *(const uint2*)&upT[(mt*16 + gid + 8)*264 + k0 + 2*tg];
                mma8(co[m], a01.x, a23.x, a01.y, a23.y, bb.x, bb.y);
            }
        }

        if (half && gid == 0) {
            den_s[q0 + 2*tg    ] = co[1][0];
            den_s[q0 + 2*tg + 1] = co[1][1];
        }
        __syncthreads();

        int qq = q0 + 2*tg;
        float i0 = 1.f / den_s[qq];
        float i1 = 1.f / den_s[qq + 1];
        float* ob = out + ((size_t)head*NSEQ + t0)*DH;
        int nst = half ? 1 : 3;
        for (int m = 0; m < nst; m++) {
            int d = (mtb + m)*16 + gid;
            ob[(size_t)(qq    )*DH + d    ] = co[m][0]*i0;
            ob[(size_t)(qq + 1)*DH + d    ] = co[m][1]*i1;
            ob[(size_t)(qq    )*DH + d + 8] = co[m][2]*i0;
            ob[(size_t)(qq + 1)*DH + d + 8] = co[m][3]*i1;
        }
    }
}

extern "C" void kernel_launch(void* const* d_in, const int* in_sizes, int n_in,
                              void* d_out, int out_size) {
    const float* q    = (const float*)d_in[0];
    const float* k    = (const float*)d_in[1];
    const float* v    = (const float*)d_in[2];
    const float* proj = (const float*)d_in[3];
    float* out = (float*)d_out;

    size_t smem_pr  = (size_t)(2*256*72 + 2*128*72) * sizeof(unsigned);             // 221184
    size_t smem_cs  = (size_t)(256*72 + 64*72 + 512) * sizeof(unsigned);            // 94208
    size_t smem_out = (size_t)(16896 + 21120 + 5760 + 4608) * sizeof(unsigned);     // 193536
    cudaFuncSetAttribute(proj_kernel,     cudaFuncAttributeMaxDynamicSharedMemorySize, (int)smem_pr);
    cudaFuncSetAttribute(chunksum_kernel, cudaFuncAttributeMaxDynamicSharedMemorySize, (int)smem_cs);
    cudaFuncSetAttribute(out_kernel,      cudaFuncAttributeMaxDynamicSharedMemorySize, (int)smem_out);

    init_kernel<<<1, 32>>>();
    proj_kernel<<<BH*16, 512, smem_pr>>>(q, k, proj);
    chunksum_kernel<<<BH*NC, 512, smem_cs>>>(v);
    prefix_kernel<<<dim3(BH, 65), 256>>>();
    out_kernel<<<BH*NC, 512, smem_out>>>(v, out);
}